// round 4
// baseline (speedup 1.0000x reference)
#include <cuda_runtime.h>

#define NM 8192
#define NB 2
#define V0 642
#define V1 2562
#define V2 10242
#define E0 1920
#define E1 7680
#define E2 30720
#define NUNITS 3584
#define GRID_CHAMFER 592
#define EPI_BLOCKS 723
#define INF_F __int_as_float(0x7f800000)

// ---------------- scratch (device globals; no allocation) ----------------
// A partials: per level, [(b*V+v)*32 + slice] -> {f32 bits of d'=min(g2-2p.g), global argmin m}
__device__ uint2        g_pA[2 * (V0 + V1 + V2) * 32];
// B partials: per level, [(vt*2+b)*NM + m] -> f32 d'=min(p2-2g.p)
__device__ float        g_pB[(6 + 21 + 81) * 2 * NM];
__device__ double       g_acc[18]; // 0-2 predsum 3-5 gtsum 6-8 edge 9-11 normal 12-14 lap 15-17 move
__device__ unsigned int g_work;    // work-stealing ticket (reset by epi's final block)
__device__ unsigned int g_done;

// per-level bases
#define PA_BASE0 0
#define PA_BASE1 (2*V0*32)               // 41088
#define PA_BASE2 (2*V0*32 + 2*V1*32)     // 205056
#define PB_BASE0 0
#define PB_BASE1 (6*2*NM)                // 98304
#define PB_BASE2 (6*2*NM + 21*2*NM)      // 442368

// ---------------- helpers ----------------
static __device__ __forceinline__ unsigned long long pack2(float lo, float hi) {
    unsigned long long r;
    asm("mov.b64 %0,{%1,%2};" : "=l"(r) : "f"(lo), "f"(hi));
    return r;
}
static __device__ __forceinline__ void unpack2(unsigned long long v, float& lo, float& hi) {
    asm("mov.b64 {%0,%1},%2;" : "=f"(lo), "=f"(hi) : "l"(v));
}
static __device__ __forceinline__ unsigned long long fma2(unsigned long long a,
                                                          unsigned long long b,
                                                          unsigned long long c) {
    unsigned long long d;
    asm("fma.rn.f32x2 %0,%1,%2,%3;" : "=l"(d) : "l"(a), "l"(b), "l"(c));
    return d;
}

// ---------------- chamfer inner loop ----------------
template <int NJ, int K, bool ARGMIN>
static __device__ __forceinline__ void inner(
    const ulonglong2* __restrict__ sXY, const ulonglong2* __restrict__ sZW,
    const unsigned long long* ax2, const unsigned long long* ay2, const unsigned long long* az2,
    float* bd, int* bm, int mbase)
{
#pragma unroll 4
    for (int j = 0; j < NJ; j++) {
        ulonglong2 xy = sXY[j];
        ulonglong2 zw = sZW[j];
#pragma unroll
        for (int k = 0; k < K; k++) {
            unsigned long long d = fma2(az2[k], zw.x, zw.y);
            d = fma2(ay2[k], xy.y, d);
            d = fma2(ax2[k], xy.x, d);
            float lo, hi;
            unpack2(d, lo, hi);
            if (ARGMIN) {
                if (lo < bd[k]) { bd[k] = lo; bm[k] = mbase + 2 * j; }
                if (hi < bd[k]) { bd[k] = hi; bm[k] = mbase + 2 * j + 1; }
            } else {
                bd[k] = fminf(bd[k], lo);
                bd[k] = fminf(bd[k], hi);
            }
        }
    }
}

// ---------------- persistent work-stealing chamfer ----------------
// unit map: A2 [0,1344) B2 [1344,2640) A1 [2640,3024) B1 [3024,3360) A0 [3360,3488) B0 [3488,3584)
// A unit: (chunk of 512 pred, slice of 256 gt, b); B unit: (chunk of 1024 gt, vtile of 128 pred, b)
__global__ __launch_bounds__(256, 4) void chamfer_kernel(
    const float* __restrict__ p0l, const float* __restrict__ p1l, const float* __restrict__ p2l,
    const float* __restrict__ gt)
{
    __shared__ ulonglong2 sXY[128], sZW[128];
    __shared__ int s_unit;
    const int t = threadIdx.x;
    if (t == 0) s_unit = (int)atomicAdd(&g_work, 1u);
    __syncthreads();
    int unit = s_unit;

    while (unit < NUNITS) {
        int lvl, isA, u;
        if (unit < 1344)      { lvl = 2; isA = 1; u = unit; }
        else if (unit < 2640) { lvl = 2; isA = 0; u = unit - 1344; }
        else if (unit < 3024) { lvl = 1; isA = 1; u = unit - 2640; }
        else if (unit < 3360) { lvl = 1; isA = 0; u = unit - 3024; }
        else if (unit < 3488) { lvl = 0; isA = 1; u = unit - 3360; }
        else                  { lvl = 0; isA = 0; u = unit - 3488; }
        const int b = u & 1; u >>= 1;
        const float* pred = (lvl == 0) ? p0l : (lvl == 1 ? p1l : p2l);
        const int V = (lvl == 0) ? V0 : (lvl == 1 ? V1 : V2);

        if (isA) {
            const int slice = u & 31, chunk = u >> 5;
            const int mtile = slice * 256;
            if (t < 128) {
                const float2* gp = (const float2*)(gt + ((size_t)b * NM + mtile) * 3);
                float2 f0 = gp[3 * t], f1 = gp[3 * t + 1], f2 = gp[3 * t + 2];
                float x0 = f0.x, y0 = f0.y, z0 = f1.x, x1 = f1.y, y1 = f2.x, z1 = f2.y;
                sXY[t] = make_ulonglong2(pack2(x0, x1), pack2(y0, y1));
                sZW[t] = make_ulonglong2(pack2(z0, z1),
                                         pack2(x0 * x0 + y0 * y0 + z0 * z0,
                                               x1 * x1 + y1 * y1 + z1 * z1));
            }
            __syncthreads();
            if (t == 0) s_unit = (int)atomicAdd(&g_work, 1u); // prefetch next unit
            const int vb = chunk * 512 + t;
            if (vb < V) {
                unsigned long long ax2[2], ay2[2], az2[2];
                float bd[2] = {INF_F, INF_F};
                int bm[2] = {0, 0};
#pragma unroll
                for (int k = 0; k < 2; k++) {
                    float px = 0.f, py = 0.f, pz = 0.f;
                    int v = vb + 256 * k;
                    if (v < V) { const float* pp = pred + ((size_t)b * V + v) * 3; px = pp[0]; py = pp[1]; pz = pp[2]; }
                    ax2[k] = pack2(-2.f * px, -2.f * px);
                    ay2[k] = pack2(-2.f * py, -2.f * py);
                    az2[k] = pack2(-2.f * pz, -2.f * pz);
                }
                if (b == 0) inner<128, 2, true >(sXY, sZW, ax2, ay2, az2, bd, bm, mtile);
                else        inner<128, 2, false>(sXY, sZW, ax2, ay2, az2, bd, bm, mtile);
                const size_t pbase = (lvl == 0) ? PA_BASE0 : (lvl == 1 ? PA_BASE1 : PA_BASE2);
#pragma unroll
                for (int k = 0; k < 2; k++) {
                    int v = vb + 256 * k;
                    if (v < V)
                        g_pA[pbase + ((size_t)(b * V + v)) * 32 + slice] =
                            make_uint2(__float_as_uint(bd[k]), (unsigned)bm[k]);
                }
            }
            __syncthreads();
        } else {
            const int chunk = u & 7, vt = u >> 3;
            const int vtile = vt * 128;
            if (t < 64) {
                int i0 = vtile + 2 * t, i1 = i0 + 1;
                float x0 = 0.f, y0 = 0.f, z0 = 0.f, w0 = INF_F;
                float x1 = 0.f, y1 = 0.f, z1 = 0.f, w1 = INF_F;
                if (i0 < V) { const float* pp = pred + ((size_t)b * V + i0) * 3;
                              x0 = pp[0]; y0 = pp[1]; z0 = pp[2]; w0 = x0 * x0 + y0 * y0 + z0 * z0; }
                if (i1 < V) { const float* pp = pred + ((size_t)b * V + i1) * 3;
                              x1 = pp[0]; y1 = pp[1]; z1 = pp[2]; w1 = x1 * x1 + y1 * y1 + z1 * z1; }
                sXY[t] = make_ulonglong2(pack2(x0, x1), pack2(y0, y1));
                sZW[t] = make_ulonglong2(pack2(z0, z1), pack2(w0, w1));
            }
            __syncthreads();
            if (t == 0) s_unit = (int)atomicAdd(&g_work, 1u); // prefetch next unit
            const int mb = chunk * 1024 + t;
            unsigned long long ax2[4], ay2[4], az2[4];
            float bd[4] = {INF_F, INF_F, INF_F, INF_F};
            int bm[4] = {0, 0, 0, 0};
#pragma unroll
            for (int k = 0; k < 4; k++) {
                const float* gp = gt + ((size_t)b * NM + mb + 256 * k) * 3;
                float gx = gp[0], gy = gp[1], gz = gp[2];
                ax2[k] = pack2(-2.f * gx, -2.f * gx);
                ay2[k] = pack2(-2.f * gy, -2.f * gy);
                az2[k] = pack2(-2.f * gz, -2.f * gz);
            }
            inner<64, 4, false>(sXY, sZW, ax2, ay2, az2, bd, bm, 0);
            const size_t pbase = (lvl == 0) ? PB_BASE0 : (lvl == 1 ? PB_BASE1 : PB_BASE2);
#pragma unroll
            for (int k = 0; k < 4; k++)
                g_pB[pbase + (size_t)(vt * 2 + b) * NM + mb + 256 * k] = bd[k];
            __syncthreads();
        }
        unit = s_unit;
    }
}

// ---------------- merged epilogue ----------------
// blocks: edge [0,15)L0 [15,75)L1 [75,315)L2
//         finA [315,321)L0 [321,342)L1 [342,423)L2
//         finB [423,487)L0 [487,551)L1 [551,615)L2
//         lap  [615,621)L0 [621,642)L1 [642,723)L2
__global__ __launch_bounds__(256) void epi_kernel(
    const float* __restrict__ p0l, const float* __restrict__ p1l, const float* __restrict__ p2l,
    const float* __restrict__ b0l, const float* __restrict__ b1l, const float* __restrict__ b2l,
    const int* __restrict__ l0l, const int* __restrict__ l1l, const int* __restrict__ l2l,
    const int* __restrict__ e0l, const int* __restrict__ e1l, const int* __restrict__ e2l,
    const float* __restrict__ gt, const float* __restrict__ gtn,
    float* __restrict__ out)
{
    const int bk = blockIdx.x, t = threadIdx.x;
    float val = 0.f, val2 = 0.f;
    int slot = -1, slot2 = -1;

    if (bk < 315) {
        // ---- edge + normal (argmin re-reduced from contiguous A-partials, b=0) ----
        int lvl, base; const float* pred; const int* edges; int V, E; size_t pAb;
        if (bk < 15)      { lvl = 0; base = bk * 256;        pred = p0l; edges = e0l; V = V0; E = E0; pAb = PA_BASE0; }
        else if (bk < 75) { lvl = 1; base = (bk - 15) * 256; pred = p1l; edges = e1l; V = V1; E = E1; pAb = PA_BASE1; }
        else              { lvl = 2; base = (bk - 75) * 256; pred = p2l; edges = e2l; V = V2; E = E2; pAb = PA_BASE2; }
        int idx = base + t;
        if (idx < NB * E) {
            int bb = idx / E, e = idx - bb * E;
            int e0 = edges[2 * e], e1 = edges[2 * e + 1];
            const float* a = pred + ((size_t)bb * V + e0) * 3;
            const float* c = pred + ((size_t)bb * V + e1) * 3;
            float dx = a[0] - c[0], dy = a[1] - c[1], dz = a[2] - c[2];
            float sq = dx * dx + dy * dy + dz * dz;
            val = sq;
            float inv = 1.f / fmaxf(sqrtf(sq), 1e-12f);
            const uint2* q = g_pA + pAb + (size_t)e0 * 32; // b=0 row, 32 contiguous slices
            float best = INF_F; unsigned bid = 0;
#pragma unroll
            for (int s = 0; s < 32; s++) {
                uint2 qq = q[s];
                float d = __uint_as_float(qq.x);
                if (d < best) { best = d; bid = qq.y; }
            }
            const float* g = gtn + ((size_t)bb * NM + bid) * 3;
            float gx = g[0], gy = g[1], gz = g[2];
            float gi = 1.f / fmaxf(sqrtf(gx * gx + gy * gy + gz * gz), 1e-12f);
            val2 = fabsf((dx * gx + dy * gy + dz * gz) * inv * gi);
        }
        slot = 6 + lvl;
        slot2 = 9 + lvl;
    } else if (bk < 423) {
        // ---- finA: reduce 32 slice-partials, add back |p|^2 ----
        int lvl, base; const float* pred; int V; size_t pAb;
        if (bk < 321)      { lvl = 0; base = (bk - 315) * 256; pred = p0l; V = V0; pAb = PA_BASE0; }
        else if (bk < 342) { lvl = 1; base = (bk - 321) * 256; pred = p1l; V = V1; pAb = PA_BASE1; }
        else               { lvl = 2; base = (bk - 342) * 256; pred = p2l; V = V2; pAb = PA_BASE2; }
        int idx = base + t;
        if (idx < NB * V) {
            const uint2* q = g_pA + pAb + (size_t)idx * 32;
            float best = INF_F;
#pragma unroll
            for (int s = 0; s < 32; s++) {
                float d = __uint_as_float(q[s].x);
                best = fminf(best, d);
            }
            int bb = idx / V, v = idx - bb * V;
            const float* pp = pred + ((size_t)bb * V + v) * 3;
            val = best + pp[0] * pp[0] + pp[1] * pp[1] + pp[2] * pp[2];
        }
        slot = lvl;
    } else if (bk < 615) {
        // ---- finB: reduce S vtile-partials, add back |g|^2 ----
        int lvl = (bk - 423) >> 6;
        int idx = ((bk - 423) & 63) * 256 + t; // < 16384
        int S = (lvl == 0) ? 6 : (lvl == 1 ? 21 : 81);
        size_t pBb = (lvl == 0) ? PB_BASE0 : (lvl == 1 ? PB_BASE1 : PB_BASE2);
        int bb = idx >> 13, m = idx & (NM - 1);
        float best = INF_F;
        for (int vt = 0; vt < S; vt++)
            best = fminf(best, g_pB[pBb + (size_t)(vt * 2 + bb) * NM + m]);
        const float* gp = gt + ((size_t)bb * NM + m) * 3;
        val = best + gp[0] * gp[0] + gp[1] * gp[1] + gp[2] * gp[2];
        slot = 3 + lvl;
    } else {
        // ---- laplace + move ----
        int lvl, base; const float *pred, *bef; const int* lap; int V;
        if (bk < 621)      { lvl = 0; base = (bk - 615) * 256; pred = p0l; bef = b0l; lap = l0l; V = V0; }
        else if (bk < 642) { lvl = 1; base = (bk - 621) * 256; pred = p1l; bef = b1l; lap = l1l; V = V1; }
        else               { lvl = 2; base = (bk - 642) * 256; pred = p2l; bef = b2l; lap = l2l; V = V2; }
        int idx = base + t;
        if (idx < NB * V) {
            int bb = idx / V, v = idx - bb * V;
            const int* row = lap + (size_t)v * 10;
            float cnt = (float)row[9];
            float sx = 0.f, sy = 0.f, sz = 0.f;
#pragma unroll
            for (int j = 0; j < 8; j++) {
                int nid = row[j];
                if (nid >= 0) {
                    const float* pb = bef + ((size_t)bb * V + nid) * 3;
                    const float* pp = pred + ((size_t)bb * V + nid) * 3;
                    sx += pb[0] - pp[0];
                    sy += pb[1] - pp[1];
                    sz += pb[2] - pp[2];
                }
            }
            const float* bv = bef + ((size_t)bb * V + v) * 3;
            const float* pv = pred + ((size_t)bb * V + v) * 3;
            float dx = bv[0] - pv[0], dy = bv[1] - pv[1], dz = bv[2] - pv[2];
            float lx = dx - sx / cnt, ly = dy - sy / cnt, lz = dz - sz / cnt;
            val = lx * lx + ly * ly + lz * lz;
            val2 = dx * dx + dy * dy + dz * dz;
        }
        slot = 12 + lvl;
        if (lvl > 0) slot2 = 15 + lvl;
    }

#pragma unroll
    for (int o = 16; o; o >>= 1) {
        val  += __shfl_down_sync(0xffffffffu, val, o);
        val2 += __shfl_down_sync(0xffffffffu, val2, o);
    }
    if ((t & 31) == 0) {
        atomicAdd(&g_acc[slot], (double)val);
        if (slot2 >= 0) atomicAdd(&g_acc[slot2], (double)val2);
    }

    // ---- last-block combine + state reset for next replay ----
    __threadfence();
    __syncthreads();
    if (t == 0) {
        unsigned int ticket = atomicAdd(&g_done, 1u);
        if (ticket == EPI_BLOCKS - 1) {
            double a[18];
#pragma unroll
            for (int i = 0; i < 18; i++) a[i] = __ldcg(&g_acc[i]);
            const double Vd[3] = {642.0, 2562.0, 10242.0};
            const double Ed[3] = {1920.0, 7680.0, 30720.0};
            const double LAPC[3] = {0.2, 1.0, 1.0};
            double chamfer = 0, edge = 0, nrm = 0, lap = 0, move = 0;
            for (int i = 0; i < 3; i++) {
                chamfer += a[3 + i] / (2.0 * 8192.0) + a[i] / (2.0 * Vd[i]);
                edge += a[6 + i] / (2.0 * Ed[i]);
                nrm += a[9 + i] / (2.0 * Ed[i]);
                lap += LAPC[i] * a[12 + i] / (2.0 * Vd[i]);
                if (i > 0) move += LAPC[i] * a[15 + i] / (2.0 * Vd[i]);
            }
            out[0] = (float)(chamfer + 0.5 * lap + 0.1 * move + 0.1 * edge + 0.00016 * nrm);
            // reset for the next graph replay
#pragma unroll
            for (int i = 0; i < 18; i++) g_acc[i] = 0.0;
            g_work = 0u;
            g_done = 0u;
        }
    }
}

// ---------------- launcher ----------------
extern "C" void kernel_launch(void* const* d_in, const int* in_sizes, int n_in,
                              void* d_out, int out_size)
{
    (void)out_size;
    const float *pred[3] = {0, 0, 0}, *before[3] = {0, 0, 0}, *gt = 0, *gtn = 0;
    const int *lap[3] = {0, 0, 0}, *edges[3] = {0, 0, 0};
    int c0 = 0, c1 = 0, c2 = 0, cg = 0;
    for (int i = 0; i < n_in; i++) {
        int s = in_sizes[i];
        const void* p = d_in[i];
        switch (s) {
            case 3852:  if (c0++ == 0) pred[0] = (const float*)p; else before[0] = (const float*)p; break;
            case 15372: if (c1++ == 0) pred[1] = (const float*)p; else before[1] = (const float*)p; break;
            case 61452: if (c2++ == 0) pred[2] = (const float*)p; else before[2] = (const float*)p; break;
            case 49152: if (cg++ == 0) gt = (const float*)p; else gtn = (const float*)p; break;
            case 6420:   lap[0] = (const int*)p; break;
            case 25620:  lap[1] = (const int*)p; break;
            case 102420: lap[2] = (const int*)p; break;
            case 3840:   edges[0] = (const int*)p; break;
            case 15360:  edges[1] = (const int*)p; break;
            case 61440:  edges[2] = (const int*)p; break;
            default: break;
        }
    }

    chamfer_kernel<<<GRID_CHAMFER, 256>>>(pred[0], pred[1], pred[2], gt);
    epi_kernel<<<EPI_BLOCKS, 256>>>(pred[0], pred[1], pred[2],
                                    before[0], before[1], before[2],
                                    lap[0], lap[1], lap[2],
                                    edges[0], edges[1], edges[2],
                                    gt, gtn, (float*)d_out);
}

// round 5
// speedup vs baseline: 1.0412x; 1.0412x over previous
#include <cuda_runtime.h>

#define NM 8192
#define NB 2
#define V0 642
#define V1 2562
#define V2 10242
#define E0 1920
#define E1 7680
#define E2 30720
#define NUNITS 1840
#define GRID_CHAMFER 592
#define EPI_BLOCKS 723
#define INF_F __int_as_float(0x7f800000)

// ---------------- scratch (device globals; zero-init == armed for atomicMax) ----------------
__device__ unsigned long long g_keyA[NB * (V0 + V1 + V2)]; // (~ford(d') << 32) | (~m)
__device__ unsigned int       g_minB[3 * NB * NM];         // ~ford(d')
__device__ double             g_acc[18]; // 0-2 predsum 3-5 gtsum 6-8 edge 9-11 normal 12-14 lap 15-17 move
__device__ unsigned int       g_work;
__device__ unsigned int       g_done;

// ---------------- helpers ----------------
static __device__ __forceinline__ unsigned long long pack2(float lo, float hi) {
    unsigned long long r;
    asm("mov.b64 %0,{%1,%2};" : "=l"(r) : "f"(lo), "f"(hi));
    return r;
}
static __device__ __forceinline__ void unpack2(unsigned long long v, float& lo, float& hi) {
    asm("mov.b64 {%0,%1},%2;" : "=f"(lo), "=f"(hi) : "l"(v));
}
static __device__ __forceinline__ unsigned long long fma2(unsigned long long a,
                                                          unsigned long long b,
                                                          unsigned long long c) {
    unsigned long long d;
    asm("fma.rn.f32x2 %0,%1,%2,%3;" : "=l"(d) : "l"(a), "l"(b), "l"(c));
    return d;
}
// monotone float->uint (handles negatives); inv variant for atomicMax arming at 0
static __device__ __forceinline__ unsigned int ford(float f) {
    unsigned int b = __float_as_uint(f);
    return b ^ (0x80000000u | (unsigned int)(((int)b) >> 31));
}
static __device__ __forceinline__ float funord(unsigned int u) {
    unsigned int b = (u & 0x80000000u) ? (u ^ 0x80000000u) : ~u;
    return __uint_as_float(b);
}

// ---------------- chamfer inner loop (NJ packed steps over a tile) ----------------
template <int NJ, bool ARGMIN>
static __device__ __forceinline__ void inner(
    const ulonglong2* __restrict__ sXY, const ulonglong2* __restrict__ sZW,
    const unsigned long long* ax2, const unsigned long long* ay2, const unsigned long long* az2,
    float* bd, int* bm, int mbase)
{
#pragma unroll 4
    for (int j = 0; j < NJ; j++) {
        ulonglong2 xy = sXY[j];
        ulonglong2 zw = sZW[j];
#pragma unroll
        for (int k = 0; k < 4; k++) {
            unsigned long long d = fma2(az2[k], zw.x, zw.y);
            d = fma2(ay2[k], xy.y, d);
            d = fma2(ax2[k], xy.x, d);
            float lo, hi;
            unpack2(d, lo, hi);
            if (ARGMIN) {
                if (lo < bd[k]) { bd[k] = lo; bm[k] = mbase + 2 * j; }
                if (hi < bd[k]) { bd[k] = hi; bm[k] = mbase + 2 * j + 1; }
            } else {
                bd[k] = fminf(bd[k], lo);
                bd[k] = fminf(bd[k], hi);
            }
        }
    }
}

// ---------------- persistent work-stealing chamfer ----------------
// unit map (same as R3 blocks): A2 [0,704) B2 [704,1360) A1 [1360,1552) B1 [1552,1728)
//                               A0 [1728,1792) B0 [1792,1840)
__global__ __launch_bounds__(256, 4) void chamfer_kernel(
    const float* __restrict__ p0l, const float* __restrict__ p1l, const float* __restrict__ p2l,
    const float* __restrict__ gt)
{
    __shared__ ulonglong2 sXY[128], sZW[128];
    __shared__ int s_unit;
    const int t = threadIdx.x;
    if (t == 0) s_unit = (int)atomicAdd(&g_work, 1u);
    __syncthreads();
    int unit = s_unit;

    while (unit < NUNITS) {
        int lvl, isA, u;
        if (unit < 704)       { lvl = 2; isA = 1; u = unit; }
        else if (unit < 1360) { lvl = 2; isA = 0; u = unit - 704; }
        else if (unit < 1552) { lvl = 1; isA = 1; u = unit - 1360; }
        else if (unit < 1728) { lvl = 1; isA = 0; u = unit - 1552; }
        else if (unit < 1792) { lvl = 0; isA = 1; u = unit - 1728; }
        else                  { lvl = 0; isA = 0; u = unit - 1792; }
        const int b = u & 1; u >>= 1;
        const float* pred = (lvl == 0) ? p0l : (lvl == 1 ? p1l : p2l);
        const int V = (lvl == 0) ? V0 : (lvl == 1 ? V1 : V2);

        unsigned long long ax2[4], ay2[4], az2[4];
        float bd[4] = {INF_F, INF_F, INF_F, INF_F};
        int bm[4] = {0, 0, 0, 0};

        if (isA) {
            const int slice = u & 31, chunk = u >> 5;  // 32 gt-slices of 256; pred chunks of 1024
            const int mtile = slice * 256;
            if (t < 128) {
                const float2* gp = (const float2*)(gt + ((size_t)b * NM + mtile) * 3);
                float2 f0 = gp[3 * t], f1 = gp[3 * t + 1], f2 = gp[3 * t + 2];
                float x0 = f0.x, y0 = f0.y, z0 = f1.x, x1 = f1.y, y1 = f2.x, z1 = f2.y;
                sXY[t] = make_ulonglong2(pack2(x0, x1), pack2(y0, y1));
                sZW[t] = make_ulonglong2(pack2(z0, z1),
                                         pack2(x0 * x0 + y0 * y0 + z0 * z0,
                                               x1 * x1 + y1 * y1 + z1 * z1));
            }
            __syncthreads();
            if (t == 0) s_unit = (int)atomicAdd(&g_work, 1u); // prefetch next ticket
            const int vb = chunk * 1024 + t;
            if (vb < V) {
#pragma unroll
                for (int k = 0; k < 4; k++) {
                    float px = 0.f, py = 0.f, pz = 0.f;
                    int v = vb + 256 * k;
                    if (v < V) { const float* pp = pred + ((size_t)b * V + v) * 3; px = pp[0]; py = pp[1]; pz = pp[2]; }
                    ax2[k] = pack2(-2.f * px, -2.f * px);
                    ay2[k] = pack2(-2.f * py, -2.f * py);
                    az2[k] = pack2(-2.f * pz, -2.f * pz);
                }
                if (b == 0) inner<128, true >(sXY, sZW, ax2, ay2, az2, bd, bm, mtile);
                else        inner<128, false>(sXY, sZW, ax2, ay2, az2, bd, bm, mtile);
                const int keyOff = (lvl >= 1 ? NB * V0 : 0) + (lvl >= 2 ? NB * V1 : 0);
#pragma unroll
                for (int k = 0; k < 4; k++) {
                    int v = vb + 256 * k;
                    if (v < V) {
                        unsigned long long key =
                            ((unsigned long long)(~ford(bd[k])) << 32) | (unsigned int)(~bm[k]);
                        atomicMax(&g_keyA[keyOff + b * V + v], key);
                    }
                }
            }
            __syncthreads();
        } else {
            const int chunk = u & 7, slice = u >> 3;  // 8 gt-chunks of 1024; pred tiles of 256
            const int vtile = slice * 256;
            const int n = (V - vtile < 256) ? (V - vtile) : 256;
            if (t < 128) {
                float x0 = 0.f, y0 = 0.f, z0 = 0.f, w0 = INF_F;
                float x1 = 0.f, y1 = 0.f, z1 = 0.f, w1 = INF_F;
                int i0 = 2 * t, i1 = 2 * t + 1;
                if (i0 < n) { const float* pp = pred + ((size_t)b * V + vtile + i0) * 3;
                              x0 = pp[0]; y0 = pp[1]; z0 = pp[2]; w0 = x0 * x0 + y0 * y0 + z0 * z0; }
                if (i1 < n) { const float* pp = pred + ((size_t)b * V + vtile + i1) * 3;
                              x1 = pp[0]; y1 = pp[1]; z1 = pp[2]; w1 = x1 * x1 + y1 * y1 + z1 * z1; }
                sXY[t] = make_ulonglong2(pack2(x0, x1), pack2(y0, y1));
                sZW[t] = make_ulonglong2(pack2(z0, z1), pack2(w0, w1));
            }
            __syncthreads();
            if (t == 0) s_unit = (int)atomicAdd(&g_work, 1u); // prefetch next ticket
            const int mb = chunk * 1024 + t;
#pragma unroll
            for (int k = 0; k < 4; k++) {
                const float* gp = gt + ((size_t)b * NM + mb + 256 * k) * 3;
                float gx = gp[0], gy = gp[1], gz = gp[2];
                ax2[k] = pack2(-2.f * gx, -2.f * gx);
                ay2[k] = pack2(-2.f * gy, -2.f * gy);
                az2[k] = pack2(-2.f * gz, -2.f * gz);
            }
            inner<128, false>(sXY, sZW, ax2, ay2, az2, bd, bm, vtile);
            const int minOff = lvl * NB * NM;
#pragma unroll
            for (int k = 0; k < 4; k++)
                atomicMax(&g_minB[minOff + b * NM + mb + 256 * k], ~ford(bd[k]));
            __syncthreads();
        }
        unit = s_unit;
    }
}

// ---------------- merged epilogue: finA / finB / lap+move / edge+normal / combine ----------
// blocks: finA [0,6)L0 [6,27)L1 [27,108)L2; finB [108,172) [172,236) [236,300);
//         lap [300,306) [306,327) [327,408); edge [408,423) [423,483) [483,723)
__global__ __launch_bounds__(256) void epi_kernel(
    const float* __restrict__ p0l, const float* __restrict__ p1l, const float* __restrict__ p2l,
    const float* __restrict__ b0l, const float* __restrict__ b1l, const float* __restrict__ b2l,
    const int* __restrict__ l0l, const int* __restrict__ l1l, const int* __restrict__ l2l,
    const int* __restrict__ e0l, const int* __restrict__ e1l, const int* __restrict__ e2l,
    const float* __restrict__ gt, const float* __restrict__ gtn,
    float* __restrict__ out)
{
    const int bk = blockIdx.x, t = threadIdx.x;
    float val = 0.f, val2 = 0.f;
    int slot = -1, slot2 = -1;

    if (bk < 108) {
        // ---- finA: decode per-pred min keys, add back |p|^2 ----
        int lvl, base; const float* pred; int V, keyOff;
        if (bk < 6)       { lvl = 0; base = bk * 256;        pred = p0l; V = V0; keyOff = 0; }
        else if (bk < 27) { lvl = 1; base = (bk - 6) * 256;  pred = p1l; V = V1; keyOff = NB * V0; }
        else              { lvl = 2; base = (bk - 27) * 256; pred = p2l; V = V2; keyOff = NB * (V0 + V1); }
        int idx = base + t;
        if (idx < NB * V) {
            unsigned long long key = g_keyA[keyOff + idx];
            int bb = idx / V, v = idx - bb * V;
            const float* pp = pred + ((size_t)bb * V + v) * 3;
            float p2 = pp[0] * pp[0] + pp[1] * pp[1] + pp[2] * pp[2];
            val = funord(~(unsigned int)(key >> 32)) + p2;
        }
        slot = lvl;
    } else if (bk < 300) {
        // ---- finB: decode per-gt min, add back |g|^2 ----
        int lvl = (bk - 108) >> 6;
        int idx = ((bk - 108) & 63) * 256 + t; // < 16384
        unsigned int u = g_minB[lvl * NB * NM + idx];
        int bb = idx >> 13, m = idx & (NM - 1);
        const float* gp = gt + ((size_t)bb * NM + m) * 3;
        val = funord(~u) + gp[0] * gp[0] + gp[1] * gp[1] + gp[2] * gp[2];
        slot = 3 + lvl;
    } else if (bk < 408) {
        // ---- laplace + move ----
        int lvl, base; const float *pred, *bef; const int* lap; int V;
        if (bk < 306)      { lvl = 0; base = (bk - 300) * 256; pred = p0l; bef = b0l; lap = l0l; V = V0; }
        else if (bk < 327) { lvl = 1; base = (bk - 306) * 256; pred = p1l; bef = b1l; lap = l1l; V = V1; }
        else               { lvl = 2; base = (bk - 327) * 256; pred = p2l; bef = b2l; lap = l2l; V = V2; }
        int idx = base + t;
        if (idx < NB * V) {
            int bb = idx / V, v = idx - bb * V;
            const int* row = lap + (size_t)v * 10;
            float cnt = (float)row[9];
            float sx = 0.f, sy = 0.f, sz = 0.f;
#pragma unroll
            for (int j = 0; j < 8; j++) {
                int nid = row[j];
                if (nid >= 0) {
                    const float* pb = bef + ((size_t)bb * V + nid) * 3;
                    const float* pp = pred + ((size_t)bb * V + nid) * 3;
                    sx += pb[0] - pp[0];
                    sy += pb[1] - pp[1];
                    sz += pb[2] - pp[2];
                }
            }
            const float* bv = bef + ((size_t)bb * V + v) * 3;
            const float* pv = pred + ((size_t)bb * V + v) * 3;
            float dx = bv[0] - pv[0], dy = bv[1] - pv[1], dz = bv[2] - pv[2];
            float lx = dx - sx / cnt, ly = dy - sy / cnt, lz = dz - sz / cnt;
            val = lx * lx + ly * ly + lz * lz;
            val2 = dx * dx + dy * dy + dz * dz;
        }
        slot = 12 + lvl;
        if (lvl > 0) slot2 = 15 + lvl;
    } else {
        // ---- edge + normal (knn decoded from g_keyA low bits, batch 0) ----
        int lvl, base; const float* pred; const int* edges; int V, E, keyOff;
        if (bk < 423)      { lvl = 0; base = (bk - 408) * 256; pred = p0l; edges = e0l; V = V0; E = E0; keyOff = 0; }
        else if (bk < 483) { lvl = 1; base = (bk - 423) * 256; pred = p1l; edges = e1l; V = V1; E = E1; keyOff = NB * V0; }
        else               { lvl = 2; base = (bk - 483) * 256; pred = p2l; edges = e2l; V = V2; E = E2; keyOff = NB * (V0 + V1); }
        int idx = base + t;
        if (idx < NB * E) {
            int bb = idx / E, e = idx - bb * E;
            int e0 = edges[2 * e], e1 = edges[2 * e + 1];
            const float* a = pred + ((size_t)bb * V + e0) * 3;
            const float* c = pred + ((size_t)bb * V + e1) * 3;
            float dx = a[0] - c[0], dy = a[1] - c[1], dz = a[2] - c[2];
            float sq = dx * dx + dy * dy + dz * dz;
            val = sq;
            float inv = 1.f / fmaxf(sqrtf(sq), 1e-12f);
            unsigned int sel = ~(unsigned int)(g_keyA[keyOff + e0] & 0xFFFFFFFFull); // b=0 knn
            const float* g = gtn + ((size_t)bb * NM + sel) * 3;
            float gx = g[0], gy = g[1], gz = g[2];
            float gi = 1.f / fmaxf(sqrtf(gx * gx + gy * gy + gz * gz), 1e-12f);
            val2 = fabsf((dx * gx + dy * gy + dz * gz) * inv * gi);
        }
        slot = 6 + lvl;
        slot2 = 9 + lvl;
    }

#pragma unroll
    for (int o = 16; o; o >>= 1) {
        val  += __shfl_down_sync(0xffffffffu, val, o);
        val2 += __shfl_down_sync(0xffffffffu, val2, o);
    }
    if ((t & 31) == 0) {
        atomicAdd(&g_acc[slot], (double)val);
        if (slot2 >= 0) atomicAdd(&g_acc[slot2], (double)val2);
    }

    // ---- last-block combine + cheap state reset for the next replay ----
    __threadfence();
    __syncthreads();
    if (t == 0) {
        unsigned int ticket = atomicAdd(&g_done, 1u);
        if (ticket == EPI_BLOCKS - 1) {
            double a[18];
#pragma unroll
            for (int i = 0; i < 18; i++) a[i] = __ldcg(&g_acc[i]);
            const double Vd[3] = {642.0, 2562.0, 10242.0};
            const double Ed[3] = {1920.0, 7680.0, 30720.0};
            const double LAPC[3] = {0.2, 1.0, 1.0};
            double chamfer = 0, edge = 0, nrm = 0, lap = 0, move = 0;
            for (int i = 0; i < 3; i++) {
                chamfer += a[3 + i] / (2.0 * 8192.0) + a[i] / (2.0 * Vd[i]);
                edge += a[6 + i] / (2.0 * Ed[i]);
                nrm += a[9 + i] / (2.0 * Ed[i]);
                lap += LAPC[i] * a[12 + i] / (2.0 * Vd[i]);
                if (i > 0) move += LAPC[i] * a[15 + i] / (2.0 * Vd[i]);
            }
            out[0] = (float)(chamfer + 0.5 * lap + 0.1 * move + 0.1 * edge + 0.00016 * nrm);
#pragma unroll
            for (int i = 0; i < 18; i++) g_acc[i] = 0.0;
            g_work = 0u;
            g_done = 0u;
        }
    }
}

// ---------------- launcher ----------------
extern "C" void kernel_launch(void* const* d_in, const int* in_sizes, int n_in,
                              void* d_out, int out_size)
{
    (void)out_size;
    const float *pred[3] = {0, 0, 0}, *before[3] = {0, 0, 0}, *gt = 0, *gtn = 0;
    const int *lap[3] = {0, 0, 0}, *edges[3] = {0, 0, 0};
    int c0 = 0, c1 = 0, c2 = 0, cg = 0;
    for (int i = 0; i < n_in; i++) {
        int s = in_sizes[i];
        const void* p = d_in[i];
        switch (s) {
            case 3852:  if (c0++ == 0) pred[0] = (const float*)p; else before[0] = (const float*)p; break;
            case 15372: if (c1++ == 0) pred[1] = (const float*)p; else before[1] = (const float*)p; break;
            case 61452: if (c2++ == 0) pred[2] = (const float*)p; else before[2] = (const float*)p; break;
            case 49152: if (cg++ == 0) gt = (const float*)p; else gtn = (const float*)p; break;
            case 6420:   lap[0] = (const int*)p; break;
            case 25620:  lap[1] = (const int*)p; break;
            case 102420: lap[2] = (const int*)p; break;
            case 3840:   edges[0] = (const int*)p; break;
            case 15360:  edges[1] = (const int*)p; break;
            case 61440:  edges[2] = (const int*)p; break;
            default: break;
        }
    }

    chamfer_kernel<<<GRID_CHAMFER, 256>>>(pred[0], pred[1], pred[2], gt);
    epi_kernel<<<EPI_BLOCKS, 256>>>(pred[0], pred[1], pred[2],
                                    before[0], before[1], before[2],
                                    lap[0], lap[1], lap[2],
                                    edges[0], edges[1], edges[2],
                                    gt, gtn, (float*)d_out);
}

// round 6
// speedup vs baseline: 1.1796x; 1.1330x over previous
#include <cuda_runtime.h>

#define NM 8192
#define NB 2
#define V0 642
#define V1 2562
#define V2 10242
#define E0 1920
#define E1 7680
#define E2 30720
#define LAP_BLOCKS 108
#define CHAMFER_BLOCKS 1840
#define EPI_BLOCKS 615
#define INF_F __int_as_float(0x7f800000)

// ---------------- scratch (device globals; zero-init == armed for atomicMax) ----------------
__device__ unsigned long long g_keyA[NB * (V0 + V1 + V2)]; // (~ford(d') << 32) | (~m)
__device__ unsigned int       g_minB[3 * NB * NM];         // ~ford(d')
__device__ double             g_acc[18]; // 0-2 predsum 3-5 gtsum 6-8 edge 9-11 normal 12-14 lap 15-17 move
__device__ unsigned int       g_done;

// ---------------- helpers ----------------
static __device__ __forceinline__ unsigned long long pack2(float lo, float hi) {
    unsigned long long r;
    asm("mov.b64 %0,{%1,%2};" : "=l"(r) : "f"(lo), "f"(hi));
    return r;
}
static __device__ __forceinline__ void unpack2(unsigned long long v, float& lo, float& hi) {
    asm("mov.b64 {%0,%1},%2;" : "=f"(lo), "=f"(hi) : "l"(v));
}
static __device__ __forceinline__ unsigned long long fma2(unsigned long long a,
                                                          unsigned long long b,
                                                          unsigned long long c) {
    unsigned long long d;
    asm("fma.rn.f32x2 %0,%1,%2,%3;" : "=l"(d) : "l"(a), "l"(b), "l"(c));
    return d;
}
// monotone float->uint (handles negatives); stored inverted so 0 == "+inf armed"
static __device__ __forceinline__ unsigned int ford(float f) {
    unsigned int b = __float_as_uint(f);
    return b ^ (0x80000000u | (unsigned int)(((int)b) >> 31));
}
static __device__ __forceinline__ float funord(unsigned int u) {
    unsigned int b = (u & 0x80000000u) ? (u ^ 0x80000000u) : ~u;
    return __uint_as_float(b);
}

// ---------------- chamfer inner loop (128 packed steps over a 256-pt tile) ----------------
template <bool ARGMIN>
static __device__ __forceinline__ void inner_loop(
    const ulonglong2* __restrict__ sXY, const ulonglong2* __restrict__ sZW,
    const unsigned long long* ax2, const unsigned long long* ay2, const unsigned long long* az2,
    float* bd, int* bm, int mbase)
{
#pragma unroll 4
    for (int j = 0; j < 128; j++) {
        ulonglong2 xy = sXY[j];
        ulonglong2 zw = sZW[j];
#pragma unroll
        for (int k = 0; k < 4; k++) {
            unsigned long long d = fma2(az2[k], zw.x, zw.y);
            d = fma2(ay2[k], xy.y, d);
            d = fma2(ax2[k], xy.x, d);
            float lo, hi;
            unpack2(d, lo, hi);
            if (ARGMIN) {
                if (lo < bd[k]) { bd[k] = lo; bm[k] = mbase + 2 * j; }
                if (hi < bd[k]) { bd[k] = hi; bm[k] = mbase + 2 * j + 1; }
            } else {
                bd[k] = fminf(bd[k], lo);
                bd[k] = fminf(bd[k], hi);
            }
        }
    }
}

// ---------------- chamfer + lap/move (plain grid; lap blocks first for overlap) ----------
// blocks: lap [0,6)L0 [6,27)L1 [27,108)L2
//         then id=bk-108: A2 [0,704) B2 [704,1360) A1 [1360,1552) B1 [1552,1728)
//                         A0 [1728,1792) B0 [1792,1840)
__global__ __launch_bounds__(256, 4) void chamfer_kernel(
    const float* __restrict__ p0l, const float* __restrict__ p1l, const float* __restrict__ p2l,
    const float* __restrict__ b0l, const float* __restrict__ b1l, const float* __restrict__ b2l,
    const int* __restrict__ l0l, const int* __restrict__ l1l, const int* __restrict__ l2l,
    const float* __restrict__ gt)
{
    __shared__ ulonglong2 sXY[128], sZW[128];
    const int bk = blockIdx.x;
    const int t = threadIdx.x;

    if (bk < LAP_BLOCKS) {
        // ---- laplace + move (independent of chamfer results) ----
        int lvl, base; const float *pred, *bef; const int* lap; int V;
        if (bk < 6)       { lvl = 0; base = bk * 256;        pred = p0l; bef = b0l; lap = l0l; V = V0; }
        else if (bk < 27) { lvl = 1; base = (bk - 6) * 256;  pred = p1l; bef = b1l; lap = l1l; V = V1; }
        else              { lvl = 2; base = (bk - 27) * 256; pred = p2l; bef = b2l; lap = l2l; V = V2; }
        int idx = base + t;
        float val = 0.f, val2 = 0.f;
        if (idx < NB * V) {
            int bb = idx / V, v = idx - bb * V;
            const int* row = lap + (size_t)v * 10;
            float cnt = (float)row[9];
            float sx = 0.f, sy = 0.f, sz = 0.f;
#pragma unroll
            for (int j = 0; j < 8; j++) {
                int nid = row[j];
                if (nid >= 0) {
                    const float* pb = bef + ((size_t)bb * V + nid) * 3;
                    const float* pp = pred + ((size_t)bb * V + nid) * 3;
                    sx += pb[0] - pp[0];
                    sy += pb[1] - pp[1];
                    sz += pb[2] - pp[2];
                }
            }
            const float* bv = bef + ((size_t)bb * V + v) * 3;
            const float* pv = pred + ((size_t)bb * V + v) * 3;
            float dx = bv[0] - pv[0], dy = bv[1] - pv[1], dz = bv[2] - pv[2];
            float lx = dx - sx / cnt, ly = dy - sy / cnt, lz = dz - sz / cnt;
            val = lx * lx + ly * ly + lz * lz;
            val2 = dx * dx + dy * dy + dz * dz;
        }
#pragma unroll
        for (int o = 16; o; o >>= 1) {
            val  += __shfl_down_sync(0xffffffffu, val, o);
            val2 += __shfl_down_sync(0xffffffffu, val2, o);
        }
        if ((t & 31) == 0) {
            atomicAdd(&g_acc[12 + lvl], (double)val);
            if (lvl > 0) atomicAdd(&g_acc[15 + lvl], (double)val2);
        }
        return;
    }

    const int id = bk - LAP_BLOCKS;
    int lvl, isA, u;
    if (id < 704)       { lvl = 2; isA = 1; u = id; }
    else if (id < 1360) { lvl = 2; isA = 0; u = id - 704; }
    else if (id < 1552) { lvl = 1; isA = 1; u = id - 1360; }
    else if (id < 1728) { lvl = 1; isA = 0; u = id - 1552; }
    else if (id < 1792) { lvl = 0; isA = 1; u = id - 1728; }
    else                { lvl = 0; isA = 0; u = id - 1792; }
    const int b = u & 1; u >>= 1;
    int chunk, slice;
    if (isA) { slice = u & 31; chunk = u >> 5; }   // 32 M-slices of 256
    else     { chunk = u & 7;  slice = u >> 3; }   // 8 M-chunks of 1024

    const float* pred = (lvl == 0) ? p0l : (lvl == 1 ? p1l : p2l);
    const int V = (lvl == 0) ? V0 : (lvl == 1 ? V1 : V2);

    unsigned long long ax2[4], ay2[4], az2[4];
    float bd[4] = {INF_F, INF_F, INF_F, INF_F};
    int bm[4] = {0, 0, 0, 0};

    if (isA) {
        // points = pred, loop dim = gt tile (always full 256)
        const int mtile = slice * 256;
        if (t < 128) {
            const float2* gp = (const float2*)(gt + ((size_t)b * NM + mtile) * 3);
            float2 f0 = gp[3 * t], f1 = gp[3 * t + 1], f2 = gp[3 * t + 2];
            float x0 = f0.x, y0 = f0.y, z0 = f1.x, x1 = f1.y, y1 = f2.x, z1 = f2.y;
            sXY[t] = make_ulonglong2(pack2(x0, x1), pack2(y0, y1));
            sZW[t] = make_ulonglong2(pack2(z0, z1),
                                     pack2(x0 * x0 + y0 * y0 + z0 * z0,
                                           x1 * x1 + y1 * y1 + z1 * z1));
        }
        const int vb = chunk * 1024 + t;
#pragma unroll
        for (int k = 0; k < 4; k++) {
            float px = 0.f, py = 0.f, pz = 0.f;
            int v = vb + 256 * k;
            if (v < V) {
                const float* pp = pred + ((size_t)b * V + v) * 3;
                px = pp[0]; py = pp[1]; pz = pp[2];
            }
            ax2[k] = pack2(-2.f * px, -2.f * px);
            ay2[k] = pack2(-2.f * py, -2.f * py);
            az2[k] = pack2(-2.f * pz, -2.f * pz);
        }
        __syncthreads();
        if (vb < V) {
            if (b == 0) inner_loop<true >(sXY, sZW, ax2, ay2, az2, bd, bm, mtile);
            else        inner_loop<false>(sXY, sZW, ax2, ay2, az2, bd, bm, mtile);
            const int keyOff = (lvl >= 1 ? NB * V0 : 0) + (lvl >= 2 ? NB * V1 : 0);
#pragma unroll
            for (int k = 0; k < 4; k++) {
                int v = vb + 256 * k;
                if (v < V) {
                    unsigned long long key =
                        ((unsigned long long)(~ford(bd[k])) << 32) | (unsigned int)(~bm[k]);
                    atomicMax(&g_keyA[keyOff + b * V + v], key);
                }
            }
        }
    } else {
        // points = gt (always valid), loop dim = pred tile (pad tail with +inf)
        const int vtile = slice * 256;
        const int n = (V - vtile < 256) ? (V - vtile) : 256;
        if (t < 128) {
            float x0 = 0.f, y0 = 0.f, z0 = 0.f, w0 = INF_F;
            float x1 = 0.f, y1 = 0.f, z1 = 0.f, w1 = INF_F;
            int i0 = 2 * t, i1 = 2 * t + 1;
            if (i0 < n) {
                const float* pp = pred + ((size_t)b * V + vtile + i0) * 3;
                x0 = pp[0]; y0 = pp[1]; z0 = pp[2];
                w0 = x0 * x0 + y0 * y0 + z0 * z0;
            }
            if (i1 < n) {
                const float* pp = pred + ((size_t)b * V + vtile + i1) * 3;
                x1 = pp[0]; y1 = pp[1]; z1 = pp[2];
                w1 = x1 * x1 + y1 * y1 + z1 * z1;
            }
            sXY[t] = make_ulonglong2(pack2(x0, x1), pack2(y0, y1));
            sZW[t] = make_ulonglong2(pack2(z0, z1), pack2(w0, w1));
        }
        const int mb = chunk * 1024 + t;
#pragma unroll
        for (int k = 0; k < 4; k++) {
            const float* gp = gt + ((size_t)b * NM + mb + 256 * k) * 3;
            float gx = gp[0], gy = gp[1], gz = gp[2];
            ax2[k] = pack2(-2.f * gx, -2.f * gx);
            ay2[k] = pack2(-2.f * gy, -2.f * gy);
            az2[k] = pack2(-2.f * gz, -2.f * gz);
        }
        __syncthreads();
        inner_loop<false>(sXY, sZW, ax2, ay2, az2, bd, bm, vtile);
        const int minOff = lvl * NB * NM;
#pragma unroll
        for (int k = 0; k < 4; k++)
            atomicMax(&g_minB[minOff + b * NM + mb + 256 * k], ~ford(bd[k]));
    }
}

// ---------------- epilogue: edge+normal / finA / finB / combine ----------
// blocks: edge [0,15)L0 [15,75)L1 [75,315)L2
//         finA [315,321)L0 [321,342)L1 [342,423)L2
//         finB [423,487)L0 [487,551)L1 [551,615)L2
__global__ __launch_bounds__(256) void epi_kernel(
    const float* __restrict__ p0l, const float* __restrict__ p1l, const float* __restrict__ p2l,
    const int* __restrict__ e0l, const int* __restrict__ e1l, const int* __restrict__ e2l,
    const float* __restrict__ gt, const float* __restrict__ gtn,
    float* __restrict__ out)
{
    const int bk = blockIdx.x, t = threadIdx.x;
    float val = 0.f, val2 = 0.f;
    int slot = -1, slot2 = -1;

    if (bk < 315) {
        // ---- edge + normal (knn decoded from g_keyA low bits, batch 0) ----
        int lvl, base; const float* pred; const int* edges; int V, E, keyOff;
        if (bk < 15)      { lvl = 0; base = bk * 256;        pred = p0l; edges = e0l; V = V0; E = E0; keyOff = 0; }
        else if (bk < 75) { lvl = 1; base = (bk - 15) * 256; pred = p1l; edges = e1l; V = V1; E = E1; keyOff = NB * V0; }
        else              { lvl = 2; base = (bk - 75) * 256; pred = p2l; edges = e2l; V = V2; E = E2; keyOff = NB * (V0 + V1); }
        int idx = base + t;
        if (idx < NB * E) {
            int bb = idx / E, e = idx - bb * E;
            int e0 = edges[2 * e], e1 = edges[2 * e + 1];
            const float* a = pred + ((size_t)bb * V + e0) * 3;
            const float* c = pred + ((size_t)bb * V + e1) * 3;
            float dx = a[0] - c[0], dy = a[1] - c[1], dz = a[2] - c[2];
            float sq = dx * dx + dy * dy + dz * dz;
            val = sq;
            float inv = 1.f / fmaxf(sqrtf(sq), 1e-12f);
            unsigned int sel = ~(unsigned int)(g_keyA[keyOff + e0] & 0xFFFFFFFFull); // b=0 knn
            const float* g = gtn + ((size_t)bb * NM + sel) * 3;
            float gx = g[0], gy = g[1], gz = g[2];
            float gi = 1.f / fmaxf(sqrtf(gx * gx + gy * gy + gz * gz), 1e-12f);
            val2 = fabsf((dx * gx + dy * gy + dz * gz) * inv * gi);
        }
        slot = 6 + lvl;
        slot2 = 9 + lvl;
    } else if (bk < 423) {
        // ---- finA: decode per-pred min keys, add back |p|^2 ----
        int lvl, base; const float* pred; int V, keyOff;
        if (bk < 321)      { lvl = 0; base = (bk - 315) * 256; pred = p0l; V = V0; keyOff = 0; }
        else if (bk < 342) { lvl = 1; base = (bk - 321) * 256; pred = p1l; V = V1; keyOff = NB * V0; }
        else               { lvl = 2; base = (bk - 342) * 256; pred = p2l; V = V2; keyOff = NB * (V0 + V1); }
        int idx = base + t;
        if (idx < NB * V) {
            unsigned long long key = g_keyA[keyOff + idx];
            int bb = idx / V, v = idx - bb * V;
            const float* pp = pred + ((size_t)bb * V + v) * 3;
            float p2 = pp[0] * pp[0] + pp[1] * pp[1] + pp[2] * pp[2];
            val = funord(~(unsigned int)(key >> 32)) + p2;
        }
        slot = lvl;
    } else {
        // ---- finB: decode per-gt min, add back |g|^2 ----
        int lvl = (bk - 423) >> 6;
        int idx = ((bk - 423) & 63) * 256 + t; // < 16384
        unsigned int u = g_minB[lvl * NB * NM + idx];
        int bb = idx >> 13, m = idx & (NM - 1);
        const float* gp = gt + ((size_t)bb * NM + m) * 3;
        val = funord(~u) + gp[0] * gp[0] + gp[1] * gp[1] + gp[2] * gp[2];
        slot = 3 + lvl;
    }

#pragma unroll
    for (int o = 16; o; o >>= 1) {
        val  += __shfl_down_sync(0xffffffffu, val, o);
        val2 += __shfl_down_sync(0xffffffffu, val2, o);
    }
    if ((t & 31) == 0) {
        atomicAdd(&g_acc[slot], (double)val);
        if (slot2 >= 0) atomicAdd(&g_acc[slot2], (double)val2);
    }

    // ---- last-block combine + cheap state reset for the next replay ----
    __threadfence();
    __syncthreads();
    if (t == 0) {
        unsigned int ticket = atomicAdd(&g_done, 1u);
        if (ticket == EPI_BLOCKS - 1) {
            double a[18];
#pragma unroll
            for (int i = 0; i < 18; i++) a[i] = __ldcg(&g_acc[i]);
            const double Vd[3] = {642.0, 2562.0, 10242.0};
            const double Ed[3] = {1920.0, 7680.0, 30720.0};
            const double LAPC[3] = {0.2, 1.0, 1.0};
            double chamfer = 0, edge = 0, nrm = 0, lap = 0, move = 0;
            for (int i = 0; i < 3; i++) {
                chamfer += a[3 + i] / (2.0 * 8192.0) + a[i] / (2.0 * Vd[i]);
                edge += a[6 + i] / (2.0 * Ed[i]);
                nrm += a[9 + i] / (2.0 * Ed[i]);
                lap += LAPC[i] * a[12 + i] / (2.0 * Vd[i]);
                if (i > 0) move += LAPC[i] * a[15 + i] / (2.0 * Vd[i]);
            }
            out[0] = (float)(chamfer + 0.5 * lap + 0.1 * move + 0.1 * edge + 0.00016 * nrm);
#pragma unroll
            for (int i = 0; i < 18; i++) g_acc[i] = 0.0;
            g_done = 0u;
        }
    }
}

// ---------------- launcher ----------------
extern "C" void kernel_launch(void* const* d_in, const int* in_sizes, int n_in,
                              void* d_out, int out_size)
{
    (void)out_size;
    const float *pred[3] = {0, 0, 0}, *before[3] = {0, 0, 0}, *gt = 0, *gtn = 0;
    const int *lap[3] = {0, 0, 0}, *edges[3] = {0, 0, 0};
    int c0 = 0, c1 = 0, c2 = 0, cg = 0;
    for (int i = 0; i < n_in; i++) {
        int s = in_sizes[i];
        const void* p = d_in[i];
        switch (s) {
            case 3852:  if (c0++ == 0) pred[0] = (const float*)p; else before[0] = (const float*)p; break;
            case 15372: if (c1++ == 0) pred[1] = (const float*)p; else before[1] = (const float*)p; break;
            case 61452: if (c2++ == 0) pred[2] = (const float*)p; else before[2] = (const float*)p; break;
            case 49152: if (cg++ == 0) gt = (const float*)p; else gtn = (const float*)p; break;
            case 6420:   lap[0] = (const int*)p; break;
            case 25620:  lap[1] = (const int*)p; break;
            case 102420: lap[2] = (const int*)p; break;
            case 3840:   edges[0] = (const int*)p; break;
            case 15360:  edges[1] = (const int*)p; break;
            case 61440:  edges[2] = (const int*)p; break;
            default: break;
        }
    }

    chamfer_kernel<<<LAP_BLOCKS + CHAMFER_BLOCKS, 256>>>(
        pred[0], pred[1], pred[2],
        before[0], before[1], before[2],
        lap[0], lap[1], lap[2], gt);
    epi_kernel<<<EPI_BLOCKS, 256>>>(pred[0], pred[1], pred[2],
                                    edges[0], edges[1], edges[2],
                                    gt, gtn, (float*)d_out);
}